// round 11
// baseline (speedup 1.0000x reference)
#include <cuda_runtime.h>
#include <math.h>
#include <stdint.h>

// Problem constants (fixed by the reference)
#define Nn 20000
#define Ee 320000
#define Dd 128
#define Kk 8
#define Hh 64
#define Ll 3
#define FULL 0xffffffffu

#define NBLK 5000                 // agg blocks (4 nodes each)
#define TILES 157                 // 128-node gemm tiles (last tile: 32 nodes)
#define NUNITS (TILES * Kk)       // 1256 (tile, head) gemm units
#define RESERVE_POS (NBLK - 400)  // last 400 completers stay to drain queue

// -------- device scratch (static globals; no allocation) --------
__device__ float g_S[(size_t)Nn * Kk * Dd];   // 81.92 MB per-node weighted sums
__device__ float g_v[Kk * Dd];                // folded (W_enc*attn_l)/3
__device__ int   g_deg[Nn];
__device__ int   g_beg[Nn];
__device__ int   g_cur[Nn];
__device__ int   g_perm[Ee];
__device__ int   g_ctr;
__device__ unsigned g_tdone[TILES];           // per-tile agg completion counters
__device__ int      g_qtiles[TILES];          // ready-tile queue storage
__device__ unsigned g_qslot;                  // queue write-slot counter
__device__ unsigned g_qtail;                  // committed tiles in queue
__device__ unsigned g_uhead;                  // consumed (tile,head) units
__device__ unsigned g_aggdone;                // agg blocks completed

// ---------------------------------------------------------------
// K0: fold v[k][d] = (1/3)*sum_h W_enc[d,kH+h]*attn_l[k,h];
//     zero all counters
// ---------------------------------------------------------------
__global__ void k_prep(const float* __restrict__ We, const float* __restrict__ al) {
    __shared__ float al_sh[Kk * Hh];
    int t = threadIdx.x;                // 1024 threads
    if (t < Kk * Hh) al_sh[t] = al[t];
    for (int i = t; i < Nn; i += 1024) g_deg[i] = 0;
    if (t < TILES) { g_tdone[t] = 0u; g_qtiles[t] = -1; }
    if (t == 0) {
        g_ctr = 0; g_qslot = 0u; g_qtail = 0u; g_uhead = 0u; g_aggdone = 0u;
    }
    __syncthreads();
    int k = t >> 7;
    int d = t & 127;
    const float* wrow = We + (size_t)d * (Kk * Hh) + k * Hh;
    const float* arow = al_sh + k * Hh;
    float s = 0.f;
#pragma unroll 8
    for (int h = 0; h < Hh; ++h) s = fmaf(wrow[h], arow[h], s);
    g_v[k * Dd + d] = s * (1.f / 3.f);
}

// ---------------------------------------------------------------
// K1: histogram of dst
// ---------------------------------------------------------------
__global__ void k_hist(const int* __restrict__ dst) {
    int e = blockIdx.x * blockDim.x + threadIdx.x;
    if (e < Ee) atomicAdd(&g_deg[dst[e]], 1);
}

// ---------------------------------------------------------------
// K2: order-free offset assignment: warp prefix + one atomicAdd/warp.
// ---------------------------------------------------------------
__global__ void k_off() {
    int n = blockIdx.x * blockDim.x + threadIdx.x;
    int lane = threadIdx.x & 31;
    int d = (n < Nn) ? g_deg[n] : 0;
    int pre = d;
#pragma unroll
    for (int o = 1; o < 32; o <<= 1) {
        int u = __shfl_up_sync(FULL, pre, o);
        if (lane >= o) pre += u;
    }
    int tot = __shfl_sync(FULL, pre, 31);
    int base = 0;
    if (lane == 31) base = atomicAdd(&g_ctr, tot);
    base = __shfl_sync(FULL, base, 31);
    int beg = base + pre - d;
    if (n < Nn) { g_beg[n] = beg; g_cur[n] = beg; }
}

// ---------------------------------------------------------------
// K3: scatter edge ids into per-dst contiguous ranges
// ---------------------------------------------------------------
__global__ void k_scatter(const int* __restrict__ dst) {
    int e = blockIdx.x * blockDim.x + threadIdx.x;
    if (e < Ee) {
        int pos = atomicAdd(&g_cur[dst[e]], 1);
        g_perm[pos] = e;
    }
}

// ---------------------------------------------------------------
// 9-shuffle reduction of 8 per-lane partials over the warp.
// Lane ends with full sum of value k(lane) = bitrev3(lane&7).
// Inverse map (source lane for k): SRC = {0,4,2,6,1,5,3,7}
// ---------------------------------------------------------------
__device__ __forceinline__ float reduce8_fast(float v[8], int lane) {
    bool b0 = lane & 1;
    float q0 = b0 ? v[4] : v[0], r0 = b0 ? v[0] : v[4];
    float q1 = b0 ? v[5] : v[1], r1 = b0 ? v[1] : v[5];
    float q2 = b0 ? v[6] : v[2], r2 = b0 ? v[2] : v[6];
    float q3 = b0 ? v[7] : v[3], r3 = b0 ? v[3] : v[7];
    q0 += __shfl_xor_sync(FULL, r0, 1);
    q1 += __shfl_xor_sync(FULL, r1, 1);
    q2 += __shfl_xor_sync(FULL, r2, 1);
    q3 += __shfl_xor_sync(FULL, r3, 1);
    bool b1 = lane & 2;
    float s0 = b1 ? q2 : q0, t0 = b1 ? q0 : q2;
    float s1 = b1 ? q3 : q1, t1 = b1 ? q1 : q3;
    s0 += __shfl_xor_sync(FULL, t0, 2);
    s1 += __shfl_xor_sync(FULL, t1, 2);
    bool b2 = lane & 4;
    float u0 = b2 ? s1 : s0, u1 = b2 ? s0 : s1;
    u0 += __shfl_xor_sync(FULL, u1, 4);
    u0 += __shfl_xor_sync(FULL, u0, 8);
    u0 += __shfl_xor_sync(FULL, u0, 16);
    return u0;
}

// ---------------------------------------------------------------
// K4 fused, work-stealing.  Every block: (1) agg 4 nodes (warp-per-
// node, R6 body), (2) publish tile completion, (3) become a gemm
// worker: CAS-claim (tile,head) units from the ready queue.  A block
// with no ready unit exits immediately unless it is among the last
// 400 agg completers (those stay and drain the queue).  CAS-bounded
// claims never touch unpublished work -> no unbounded spinning,
// no deadlock (spinners + unlaunched <= 400 < 592 resident capacity).
// ---------------------------------------------------------------
__global__ __launch_bounds__(128, 4) void k_fused(const float* __restrict__ ef,
                                                  const float* __restrict__ nf,
                                                  const float* __restrict__ Wr,
                                                  const float* __restrict__ We,
                                                  float* __restrict__ out) {
    __shared__ __align__(16) float smem_buf[12288];   // 48 KB gemm staging
    __shared__ int sh_ctl;

    int bid = blockIdx.x;
    int t = threadIdx.x, lane = t & 31, w = t >> 5;

    // ================= Phase A: aggregate node n ======================
    {
        int n = bid * 4 + w;          // NBLK*4 == Nn exactly
        float4 vv[Kk];
#pragma unroll
        for (int k = 0; k < Kk; ++k)
            vv[k] = ((const float4*)(g_v + k * Dd))[lane];

        float er_ln;
        {
            float4 x = ((const float4*)(nf + (size_t)n * Dd))[lane];
            float tk[Kk];
#pragma unroll
            for (int k = 0; k < Kk; ++k) {
                float4 wk = ((const float4*)(Wr + k * Dd))[lane];
                float s = x.x * wk.x;
                s = fmaf(x.y, wk.y, s);
                s = fmaf(x.z, wk.z, s);
                s = fmaf(x.w, wk.w, s);
                tk[k] = s;
            }
            er_ln = reduce8_fast(tk, lane);
        }

        float4 sl[Kk];
#pragma unroll
        for (int k = 0; k < Kk; ++k) sl[k] = make_float4(0.f, 0.f, 0.f, 0.f);
        float l_run = 0.f;

        int beg = g_beg[n];
        int end = beg + g_deg[n];
        constexpr int SRC[8] = {0, 4, 2, 6, 1, 5, 3, 7};

#define LOADE(idx, A, B, C) do {                                             \
        int eid = g_perm[(idx)];                                             \
        const float4* src = (const float4*)(ef + (size_t)eid * (Ll * Dd));   \
        A = __ldcs(src + lane);                                              \
        B = __ldcs(src + lane + 32);                                         \
        C = __ldcs(src + lane + 64);                                         \
    } while (0)

#define STEP(EA, EB, EC) do {                                                \
        float4 s4;                                                           \
        s4.x = EA.x + EB.x + EC.x;                                           \
        s4.y = EA.y + EB.y + EC.y;                                           \
        s4.z = EA.z + EB.z + EC.z;                                           \
        s4.w = EA.w + EB.w + EC.w;                                           \
        float tk[Kk];                                                        \
        _Pragma("unroll")                                                    \
        for (int k = 0; k < Kk; ++k) {                                       \
            float s = s4.x * vv[k].x;                                        \
            s = fmaf(s4.y, vv[k].y, s);                                      \
            s = fmaf(s4.z, vv[k].z, s);                                      \
            s = fmaf(s4.w, vv[k].w, s);                                      \
            tk[k] = s;                                                       \
        }                                                                    \
        float e = reduce8_fast(tk, lane) + er_ln;                            \
        e = (e > 0.f) ? e : 0.01f * e;                                       \
        float p = __expf(e);                                                 \
        l_run += p;                                                          \
        _Pragma("unroll")                                                    \
        for (int k = 0; k < Kk; ++k) {                                       \
            float pk = __shfl_sync(FULL, p, SRC[k]);                         \
            sl[k].x = fmaf(pk, s4.x, sl[k].x);                               \
            sl[k].y = fmaf(pk, s4.y, sl[k].y);                               \
            sl[k].z = fmaf(pk, s4.z, sl[k].z);                               \
            sl[k].w = fmaf(pk, s4.w, sl[k].w);                               \
        }                                                                    \
    } while (0)

        float4 A0, B0, C0, A1, B1, C1;
        if (beg < end)     LOADE(beg, A0, B0, C0);
        if (beg + 1 < end) LOADE(beg + 1, A1, B1, C1);

        int i = beg;
        while (i < end) {
            {
                float4 ea = A0, eb = B0, ec = C0;
                if (i + 2 < end) LOADE(i + 2, A0, B0, C0);
                STEP(ea, eb, ec);
            }
            if (++i >= end) break;
            {
                float4 ea = A1, eb = B1, ec = C1;
                if (i + 2 < end) LOADE(i + 2, A1, B1, C1);
                STEP(ea, eb, ec);
            }
            ++i;
        }
#undef LOADE
#undef STEP

        float inv = (l_run > 0.f) ? (1.f / l_run) : 0.f;
#pragma unroll
        for (int k = 0; k < Kk; ++k) {
            float ik = __shfl_sync(FULL, inv, SRC[k]) * (1.f / 3.f);
            float4 o;
            o.x = sl[k].x * ik; o.y = sl[k].y * ik;
            o.z = sl[k].z * ik; o.w = sl[k].w * ik;
            ((float4*)(g_S + ((size_t)n * Kk + k) * Dd))[lane] = o;
        }
    }

    // ================= Phase B: publish completion ====================
    __syncthreads();
    __threadfence();
    if (t == 0) {
        int tile = bid >> 5;
        unsigned target = (tile < TILES - 1) ? 32u : (unsigned)(NBLK - 32 * (TILES - 1));
        unsigned c = atomicAdd(&g_tdone[tile], 1u) + 1u;
        if (c == target) {
            unsigned slot = atomicAdd(&g_qslot, 1u);
            g_qtiles[slot] = tile;
            __threadfence();
            atomicAdd(&g_qtail, 1u);
        }
        sh_ctl = (int)atomicAdd(&g_aggdone, 1u);
    }
    __syncthreads();
    bool reserve = (sh_ctl >= RESERVE_POS);

    // ================= Phase C: gemm worker loop ======================
    float (*Ssd)[128] = (float (*)[128])smem_buf;            // [64][128]
    float (*Wsh)[64]  = (float (*)[64])(smem_buf + 8192);    // [64][64]

    while (true) {
        if (t == 0) {
            int u = -1;
            while (true) {
                unsigned uh = *(volatile unsigned*)&g_uhead;
                if (uh >= (unsigned)NUNITS) break;
                unsigned qt;
                asm volatile("ld.acquire.gpu.u32 %0, [%1];"
                             : "=r"(qt) : "l"(&g_qtail) : "memory");
                if (uh < qt * 8u) {
                    if (atomicCAS(&g_uhead, uh, uh + 1u) == uh) { u = (int)uh; break; }
                } else {
                    if (!reserve) break;
                    __nanosleep(128);
                }
            }
            sh_ctl = u;
        }
        __syncthreads();
        int u = sh_ctl;
        if (u < 0) return;
        __threadfence();                      // acquire side for qtiles & S
        int tile = g_qtiles[u >> 3];
        int kk = u & 7;
        int n0 = tile * 128;

        int tx = t & 7, ty = t >> 3;          // 8 x 16
        int i0 = ty * 8, h0 = tx * 8;

        float acc[8][8];
#pragma unroll
        for (int a = 0; a < 8; ++a)
#pragma unroll
            for (int b = 0; b < 8; ++b) acc[a][b] = 0.f;

#pragma unroll
        for (int c = 0; c < 2; ++c) {
            __syncthreads();   // protect smem from previous use

            // load W chunk: 1024 float4
#pragma unroll
            for (int j = 0; j < 8; ++j) {
                int wi = t + j * 128;
                int dd = wi >> 4;
                int hc = wi & 15;
                ((float4*)Wsh)[wi] =
                    *((const float4*)(We + (size_t)(c * 64 + dd) * (Kk * Hh) + kk * Hh + hc * 4));
            }
            // load S chunk transposed: thread t owns node i = t
            {
                int n = n0 + t;
                if (n < Nn) {
                    const float4* src =
                        (const float4*)(g_S + ((size_t)n * Kk + kk) * Dd + c * 64);
#pragma unroll
                    for (int j = 0; j < 16; ++j) {
                        float4 v = src[j];
                        Ssd[j * 4 + 0][t] = v.x;
                        Ssd[j * 4 + 1][t] = v.y;
                        Ssd[j * 4 + 2][t] = v.z;
                        Ssd[j * 4 + 3][t] = v.w;
                    }
                } else {
#pragma unroll
                    for (int j = 0; j < 16; ++j) {
                        Ssd[j * 4 + 0][t] = 0.f;
                        Ssd[j * 4 + 1][t] = 0.f;
                        Ssd[j * 4 + 2][t] = 0.f;
                        Ssd[j * 4 + 3][t] = 0.f;
                    }
                }
            }
            __syncthreads();

#pragma unroll 4
            for (int dd = 0; dd < 64; ++dd) {
                float4 a0 = *((const float4*)&Ssd[dd][i0]);
                float4 a1 = *((const float4*)&Ssd[dd][i0 + 4]);
                float4 b0 = *((const float4*)&Wsh[dd][h0]);
                float4 b1 = *((const float4*)&Wsh[dd][h0 + 4]);
                float av[8] = {a0.x, a0.y, a0.z, a0.w, a1.x, a1.y, a1.z, a1.w};
                float bv[8] = {b0.x, b0.y, b0.z, b0.w, b1.x, b1.y, b1.z, b1.w};
#pragma unroll
                for (int ii = 0; ii < 8; ++ii)
#pragma unroll
                    for (int hh = 0; hh < 8; ++hh)
                        acc[ii][hh] = fmaf(av[ii], bv[hh], acc[ii][hh]);
            }
        }

#pragma unroll
        for (int ii = 0; ii < 8; ++ii) {
            int n = n0 + i0 + ii;
            if (n < Nn) {
                float* dst = out + (size_t)n * (Kk * Hh) + kk * Hh + h0;
                float4 v0 = make_float4(acc[ii][0], acc[ii][1], acc[ii][2], acc[ii][3]);
                float4 v1 = make_float4(acc[ii][4], acc[ii][5], acc[ii][6], acc[ii][7]);
                *((float4*)dst)       = v0;
                *((float4*)(dst + 4)) = v1;
            }
        }
        __syncthreads();   // smem safe for next unit
    }
}

// ---------------------------------------------------------------
extern "C" void kernel_launch(void* const* d_in, const int* in_sizes, int n_in,
                              void* d_out, int out_size) {
    const float* node_feat = (const float*)d_in[0];   // (N,128)
    const float* edge_feat = (const float*)d_in[1];   // (E,3,128)
    const float* W_enc     = (const float*)d_in[2];   // (128,512)
    const float* attn_l    = (const float*)d_in[3];   // (1,8,64)
    const float* W_r       = (const float*)d_in[4];   // (8,128)
    const int*   dst       = (const int*)  d_in[5];   // (E,)
    float*       out       = (float*)d_out;           // (N,8,64)

    k_prep<<<1, 1024>>>(W_enc, attn_l);
    k_hist<<<(Ee + 255) / 256, 256>>>(dst);
    k_off<<<(Nn + 255) / 256, 256>>>();
    k_scatter<<<(Ee + 255) / 256, 256>>>(dst);
    k_fused<<<NBLK, 128>>>(edge_feat, node_feat, W_r, W_enc, out);
}

// round 12
// speedup vs baseline: 3.6943x; 3.6943x over previous
#include <cuda_runtime.h>
#include <math.h>
#include <stdint.h>

// Problem constants (fixed by the reference)
#define Nn 20000
#define Ee 320000
#define Dd 128
#define Kk 8
#define Hh 64
#define Ll 3
#define FULL 0xffffffffu

// -------- device scratch (static globals; no allocation) --------
__device__ float g_S[(size_t)Nn * Kk * Dd];   // 81.92 MB  per-node weighted sums
__device__ float g_v[Kk * Dd];                // folded (W_enc*attn_l)/3  (k-major)
__device__ int   g_deg[Nn];
__device__ int   g_beg[Nn];
__device__ int   g_cur[Nn];
__device__ int   g_perm[Ee];
__device__ int   g_ctr;

// packed f32x2 helpers (Blackwell dual-FP32 pipe)
#define PK2(d, x, y) asm("mov.b64 %0, {%1, %2};" : "=l"(d) : "f"(x), "f"(y))
#define UPK2(x, y, d) asm("mov.b64 {%0, %1}, %2;" : "=f"(x), "=f"(y) : "l"(d))
#define FMA2(acc, a, b) \
    asm("fma.rn.f32x2 %0, %1, %2, %0;" : "+l"(acc) : "l"(a), "l"(b))

// ---------------------------------------------------------------
// K0: fold v[k][d] = (1/3)*sum_h W_enc[d,kH+h]*attn_l[k,h]; zero deg/ctr
// ---------------------------------------------------------------
__global__ void k_prep(const float* __restrict__ We, const float* __restrict__ al) {
    __shared__ float al_sh[Kk * Hh];
    int t = threadIdx.x;                // 1024 threads
    if (t < Kk * Hh) al_sh[t] = al[t];
    for (int i = t; i < Nn; i += 1024) g_deg[i] = 0;
    if (t == 0) g_ctr = 0;
    __syncthreads();
    int k = t >> 7;
    int d = t & 127;
    const float* wrow = We + (size_t)d * (Kk * Hh) + k * Hh;
    const float* arow = al_sh + k * Hh;
    float s = 0.f;
#pragma unroll 8
    for (int h = 0; h < Hh; ++h) s = fmaf(wrow[h], arow[h], s);
    g_v[k * Dd + d] = s * (1.f / 3.f);
}

// ---------------------------------------------------------------
// K1: histogram of dst
// ---------------------------------------------------------------
__global__ void k_hist(const int* __restrict__ dst) {
    int e = blockIdx.x * blockDim.x + threadIdx.x;
    if (e < Ee) atomicAdd(&g_deg[dst[e]], 1);
}

// ---------------------------------------------------------------
// K2: order-free offset assignment: warp prefix + one atomicAdd/warp.
// ---------------------------------------------------------------
__global__ void k_off() {
    int n = blockIdx.x * blockDim.x + threadIdx.x;
    int lane = threadIdx.x & 31;
    int d = (n < Nn) ? g_deg[n] : 0;
    int pre = d;
#pragma unroll
    for (int o = 1; o < 32; o <<= 1) {
        int u = __shfl_up_sync(FULL, pre, o);
        if (lane >= o) pre += u;
    }
    int tot = __shfl_sync(FULL, pre, 31);
    int base = 0;
    if (lane == 31) base = atomicAdd(&g_ctr, tot);
    base = __shfl_sync(FULL, base, 31);
    int beg = base + pre - d;
    if (n < Nn) { g_beg[n] = beg; g_cur[n] = beg; }
}

// ---------------------------------------------------------------
// K3: scatter edge ids into per-dst contiguous ranges
// ---------------------------------------------------------------
__global__ void k_scatter(const int* __restrict__ dst) {
    int e = blockIdx.x * blockDim.x + threadIdx.x;
    if (e < Ee) {
        int pos = atomicAdd(&g_cur[dst[e]], 1);
        g_perm[pos] = e;
    }
}

// ---------------------------------------------------------------
// 9-shuffle reduction of 8 per-lane partials over the warp.
// Lane ends with full sum of value k(lane) = bitrev3(lane&7).
// Inverse map (source lane for k): SRC = {0,4,2,6,1,5,3,7}
// ---------------------------------------------------------------
__device__ __forceinline__ float reduce8_fast(float v[8], int lane) {
    bool b0 = lane & 1;
    float q0 = b0 ? v[4] : v[0], r0 = b0 ? v[0] : v[4];
    float q1 = b0 ? v[5] : v[1], r1 = b0 ? v[1] : v[5];
    float q2 = b0 ? v[6] : v[2], r2 = b0 ? v[2] : v[6];
    float q3 = b0 ? v[7] : v[3], r3 = b0 ? v[3] : v[7];
    q0 += __shfl_xor_sync(FULL, r0, 1);
    q1 += __shfl_xor_sync(FULL, r1, 1);
    q2 += __shfl_xor_sync(FULL, r2, 1);
    q3 += __shfl_xor_sync(FULL, r3, 1);
    bool b1 = lane & 2;
    float s0 = b1 ? q2 : q0, t0 = b1 ? q0 : q2;
    float s1 = b1 ? q3 : q1, t1 = b1 ? q1 : q3;
    s0 += __shfl_xor_sync(FULL, t0, 2);
    s1 += __shfl_xor_sync(FULL, t1, 2);
    bool b2 = lane & 4;
    float u0 = b2 ? s1 : s0, u1 = b2 ? s0 : s1;
    u0 += __shfl_xor_sync(FULL, u1, 4);
    u0 += __shfl_xor_sync(FULL, u0, 8);
    u0 += __shfl_xor_sync(FULL, u0, 16);
    return u0;
}

// ---------------------------------------------------------------
// K4: warp-per-node fused pass (proven R6 body).  Register-resident,
// no smem/blocksyncs.  Lane owns d = 4*lane..4*lane+3.  No max-
// subtraction softmax.  Depth-2 software pipeline on the edge gather.
// ---------------------------------------------------------------
__global__ __launch_bounds__(128, 4) void k_agg(const float* __restrict__ ef,
                                                const float* __restrict__ nf,
                                                const float* __restrict__ Wr) {
    int t = threadIdx.x, lane = t & 31, w = t >> 5;
    int n = blockIdx.x * 4 + w;
    if (n >= Nn) return;

    float4 vv[Kk];
#pragma unroll
    for (int k = 0; k < Kk; ++k)
        vv[k] = ((const float4*)(g_v + k * Dd))[lane];

    float er_ln;
    {
        float4 x = ((const float4*)(nf + (size_t)n * Dd))[lane];
        float tk[Kk];
#pragma unroll
        for (int k = 0; k < Kk; ++k) {
            float4 wk = ((const float4*)(Wr + k * Dd))[lane];
            float s = x.x * wk.x;
            s = fmaf(x.y, wk.y, s);
            s = fmaf(x.z, wk.z, s);
            s = fmaf(x.w, wk.w, s);
            tk[k] = s;
        }
        er_ln = reduce8_fast(tk, lane);
    }

    float4 sl[Kk];
#pragma unroll
    for (int k = 0; k < Kk; ++k) sl[k] = make_float4(0.f, 0.f, 0.f, 0.f);
    float l_run = 0.f;

    int beg = g_beg[n];
    int end = beg + g_deg[n];

#define LOADE(idx, A, B, C) do {                                             \
        int eid = g_perm[(idx)];                                             \
        const float4* src = (const float4*)(ef + (size_t)eid * (Ll * Dd));   \
        A = __ldcs(src + lane);                                              \
        B = __ldcs(src + lane + 32);                                         \
        C = __ldcs(src + lane + 64);                                         \
    } while (0)

#define STEP(EA, EB, EC) do {                                                \
        float4 s4;                                                           \
        s4.x = EA.x + EB.x + EC.x;                                           \
        s4.y = EA.y + EB.y + EC.y;                                           \
        s4.z = EA.z + EB.z + EC.z;                                           \
        s4.w = EA.w + EB.w + EC.w;                                           \
        float tk[Kk];                                                        \
        _Pragma("unroll")                                                    \
        for (int k = 0; k < Kk; ++k) {                                       \
            float s = s4.x * vv[k].x;                                        \
            s = fmaf(s4.y, vv[k].y, s);                                      \
            s = fmaf(s4.z, vv[k].z, s);                                      \
            s = fmaf(s4.w, vv[k].w, s);                                      \
            tk[k] = s;                                                       \
        }                                                                    \
        float e = reduce8_fast(tk, lane) + er_ln;                            \
        e = (e > 0.f) ? e : 0.01f * e;                                       \
        float p = __expf(e);                                                 \
        l_run += p;                                                          \
        _Pragma("unroll")                                                    \
        for (int k = 0; k < Kk; ++k) {                                       \
            float pk = __shfl_sync(FULL, p, SRC[k]);                         \
            sl[k].x = fmaf(pk, s4.x, sl[k].x);                               \
            sl[k].y = fmaf(pk, s4.y, sl[k].y);                               \
            sl[k].z = fmaf(pk, s4.z, sl[k].z);                               \
            sl[k].w = fmaf(pk, s4.w, sl[k].w);                               \
        }                                                                    \
    } while (0)

    constexpr int SRC[8] = {0, 4, 2, 6, 1, 5, 3, 7};

    float4 A0, B0, C0, A1, B1, C1;
    if (beg < end)     LOADE(beg, A0, B0, C0);
    if (beg + 1 < end) LOADE(beg + 1, A1, B1, C1);

    int i = beg;
    while (i < end) {
        {
            float4 ea = A0, eb = B0, ec = C0;
            if (i + 2 < end) LOADE(i + 2, A0, B0, C0);
            STEP(ea, eb, ec);
        }
        if (++i >= end) break;
        {
            float4 ea = A1, eb = B1, ec = C1;
            if (i + 2 < end) LOADE(i + 2, A1, B1, C1);
            STEP(ea, eb, ec);
        }
        ++i;
    }
#undef LOADE
#undef STEP

    float inv = (l_run > 0.f) ? (1.f / l_run) : 0.f;
#pragma unroll
    for (int k = 0; k < Kk; ++k) {
        float ik = __shfl_sync(FULL, inv, SRC[k]) * (1.f / 3.f);
        float4 o;
        o.x = sl[k].x * ik; o.y = sl[k].y * ik;
        o.z = sl[k].z * ik; o.w = sl[k].w * ik;
        ((float4*)(g_S + ((size_t)n * Kk + k) * Dd))[lane] = o;
    }
}

// ---------------------------------------------------------------
// K5: out[n,k,:] = S[n,k,:] @ W_enc[:, kH:kH+H]
// Block: 128 nodes x 64 h for head kk.  128 threads, 8x8 microtiles.
// Inner product in fma.rn.f32x2 (packed dual-FP32): 32 FMA2 per dd
// instead of 64 FFMA -> issue-bound time halves on the fma stream.
// ---------------------------------------------------------------
__global__ __launch_bounds__(128) void k_gemm(const float* __restrict__ We,
                                              float* __restrict__ out) {
    __shared__ float Ssd[64][128];    // 32 KB, [d][node], d-major
    __shared__ float Wsh[64][64];     // 16 KB, [d][h]
    int t  = threadIdx.x;
    int kk = blockIdx.y;
    int n0 = blockIdx.x * 128;

    int tx = t & 7, ty = t >> 3;       // 8 x 16
    int i0 = ty * 8, h0 = tx * 8;

    unsigned long long acc2[8][4];     // acc2[ii][j] = (out[ii][2j], out[ii][2j+1])
#pragma unroll
    for (int a = 0; a < 8; ++a)
#pragma unroll
        for (int b = 0; b < 4; ++b) acc2[a][b] = 0ull;

#pragma unroll
    for (int c = 0; c < 2; ++c) {
        __syncthreads();   // protect smem from previous chunk's compute

        // load W chunk: 1024 float4
#pragma unroll
        for (int j = 0; j < 8; ++j) {
            int wi = t + j * 128;
            int dd = wi >> 4;
            int hc = wi & 15;
            ((float4*)Wsh)[wi] =
                *((const float4*)(We + (size_t)(c * 64 + dd) * (Kk * Hh) + kk * Hh + hc * 4));
        }
        // load S chunk transposed: thread t owns node i = t
        {
            int n = n0 + t;
            if (n < Nn) {
                const float4* src =
                    (const float4*)(g_S + ((size_t)n * Kk + kk) * Dd + c * 64);
#pragma unroll
                for (int j = 0; j < 16; ++j) {
                    float4 v = src[j];
                    Ssd[j * 4 + 0][t] = v.x;
                    Ssd[j * 4 + 1][t] = v.y;
                    Ssd[j * 4 + 2][t] = v.z;
                    Ssd[j * 4 + 3][t] = v.w;
                }
            } else {
#pragma unroll
                for (int j = 0; j < 16; ++j) {
                    Ssd[j * 4 + 0][t] = 0.f;
                    Ssd[j * 4 + 1][t] = 0.f;
                    Ssd[j * 4 + 2][t] = 0.f;
                    Ssd[j * 4 + 3][t] = 0.f;
                }
            }
        }
        __syncthreads();

#pragma unroll 4
        for (int dd = 0; dd < 64; ++dd) {
            float4 a0 = *((const float4*)&Ssd[dd][i0]);
            float4 a1 = *((const float4*)&Ssd[dd][i0 + 4]);
            float4 b0 = *((const float4*)&Wsh[dd][h0]);
            float4 b1 = *((const float4*)&Wsh[dd][h0 + 4]);
            unsigned long long bp0, bp1, bp2, bp3;
            PK2(bp0, b0.x, b0.y);
            PK2(bp1, b0.z, b0.w);
            PK2(bp2, b1.x, b1.y);
            PK2(bp3, b1.z, b1.w);
            float av[8] = {a0.x, a0.y, a0.z, a0.w, a1.x, a1.y, a1.z, a1.w};
#pragma unroll
            for (int ii = 0; ii < 8; ++ii) {
                unsigned long long ap;
                PK2(ap, av[ii], av[ii]);
                FMA2(acc2[ii][0], ap, bp0);
                FMA2(acc2[ii][1], ap, bp1);
                FMA2(acc2[ii][2], ap, bp2);
                FMA2(acc2[ii][3], ap, bp3);
            }
        }
    }

#pragma unroll
    for (int ii = 0; ii < 8; ++ii) {
        int n = n0 + i0 + ii;
        if (n < Nn) {
            float o0, o1, o2, o3, o4, o5, o6, o7;
            UPK2(o0, o1, acc2[ii][0]);
            UPK2(o2, o3, acc2[ii][1]);
            UPK2(o4, o5, acc2[ii][2]);
            UPK2(o6, o7, acc2[ii][3]);
            float* dst = out + (size_t)n * (Kk * Hh) + kk * Hh + h0;
            *((float4*)dst)       = make_float4(o0, o1, o2, o3);
            *((float4*)(dst + 4)) = make_float4(o4, o5, o6, o7);
        }
    }
}

// ---------------------------------------------------------------
extern "C" void kernel_launch(void* const* d_in, const int* in_sizes, int n_in,
                              void* d_out, int out_size) {
    const float* node_feat = (const float*)d_in[0];   // (N,128)
    const float* edge_feat = (const float*)d_in[1];   // (E,3,128)
    const float* W_enc     = (const float*)d_in[2];   // (128,512)
    const float* attn_l    = (const float*)d_in[3];   // (1,8,64)
    const float* W_r       = (const float*)d_in[4];   // (8,128)
    const int*   dst       = (const int*)  d_in[5];   // (E,)
    float*       out       = (float*)d_out;           // (N,8,64)

    k_prep<<<1, 1024>>>(W_enc, attn_l);
    k_hist<<<(Ee + 255) / 256, 256>>>(dst);
    k_off<<<(Nn + 255) / 256, 256>>>();
    k_scatter<<<(Ee + 255) / 256, 256>>>(dst);
    k_agg<<<(Nn + 3) / 4, 128>>>(edge_feat, node_feat, W_r);
    k_gemm<<<dim3((Nn + 127) / 128, Kk), 128>>>(W_enc, out);
}

// round 13
// speedup vs baseline: 3.7595x; 1.0177x over previous
#include <cuda_runtime.h>
#include <math.h>
#include <stdint.h>

// Problem constants (fixed by the reference)
#define Nn 20000
#define Ee 320000
#define Dd 128
#define Kk 8
#define Hh 64
#define Ll 3
#define FULL 0xffffffffu

// -------- device scratch (static globals; no allocation) --------
// Invariant maintained across calls: g_deg == 0 and g_ctr == 0 at entry
// (true at load via zero-init; restored by k_scatter each call).
__device__ float g_S[(size_t)Nn * Kk * Dd];   // 81.92 MB  per-node weighted sums
__device__ float g_v[Kk * Dd];                // folded (W_enc*attn_l)/3  (k-major)
__device__ int   g_deg[Nn];
__device__ int   g_beg[Nn];
__device__ int   g_cur[Nn];                   // after scatter: g_cur[n] == end(n)
__device__ int   g_perm[Ee];
__device__ int   g_ctr;

// packed f32x2 helpers (Blackwell dual-FP32 pipe; harmless if lowered)
#define PK2(d, x, y) asm("mov.b64 %0, {%1, %2};" : "=l"(d) : "f"(x), "f"(y))
#define UPK2(x, y, d) asm("mov.b64 {%0, %1}, %2;" : "=f"(x), "=f"(y) : "l"(d))
#define FMA2(acc, a, b) \
    asm("fma.rn.f32x2 %0, %1, %2, %0;" : "+l"(acc) : "l"(a), "l"(b))

// ---------------------------------------------------------------
// K1: histogram of dst (4 edges/thread via int4) + block 0 folds
//     g_v[k][d] = (1/3)*sum_h W_enc[d,kH+h]*attn_l[k,h]
// Requires g_deg == 0 at entry (zero-init / restored by k_scatter).
// ---------------------------------------------------------------
__global__ __launch_bounds__(256) void k_hist(const int4* __restrict__ dst4,
                                              const float* __restrict__ We,
                                              const float* __restrict__ al) {
    int t = threadIdx.x;
    int i = blockIdx.x * 256 + t;
    if (i < Ee / 4) {
        int4 d = dst4[i];
        atomicAdd(&g_deg[d.x], 1);
        atomicAdd(&g_deg[d.y], 1);
        atomicAdd(&g_deg[d.z], 1);
        atomicAdd(&g_deg[d.w], 1);
    }
    if (blockIdx.x == 0) {
        __shared__ float al_sh[Kk * Hh];
        if (t < 256) { al_sh[t] = al[t]; al_sh[t + 256] = al[t + 256]; }
        __syncthreads();
#pragma unroll
        for (int p = t; p < Kk * Dd; p += 256) {
            int k = p >> 7, d = p & 127;
            const float* wrow = We + (size_t)d * (Kk * Hh) + k * Hh;
            const float* arow = al_sh + k * Hh;
            float s = 0.f;
#pragma unroll 8
            for (int h = 0; h < Hh; ++h) s = fmaf(wrow[h], arow[h], s);
            g_v[p] = s * (1.f / 3.f);
        }
    }
}

// ---------------------------------------------------------------
// K2: order-free offset assignment: warp prefix + one atomicAdd/warp.
// Requires g_ctr == 0 at entry (zero-init / restored by k_scatter).
// ---------------------------------------------------------------
__global__ void k_off() {
    int n = blockIdx.x * blockDim.x + threadIdx.x;
    int lane = threadIdx.x & 31;
    int d = (n < Nn) ? g_deg[n] : 0;
    int pre = d;
#pragma unroll
    for (int o = 1; o < 32; o <<= 1) {
        int u = __shfl_up_sync(FULL, pre, o);
        if (lane >= o) pre += u;
    }
    int tot = __shfl_sync(FULL, pre, 31);
    int base = 0;
    if (lane == 31) base = atomicAdd(&g_ctr, tot);
    base = __shfl_sync(FULL, base, 31);
    int beg = base + pre - d;
    if (n < Nn) { g_beg[n] = beg; g_cur[n] = beg; }
}

// ---------------------------------------------------------------
// K3: scatter edge ids into per-dst contiguous ranges (4 edges/thread)
//     + restore the g_deg/g_ctr == 0 invariant for the next call.
//     Leaves g_cur[n] == end(n) for k_agg.
// ---------------------------------------------------------------
__global__ __launch_bounds__(256) void k_scatter(const int4* __restrict__ dst4) {
    int i = blockIdx.x * 256 + threadIdx.x;
    if (i < Ee / 4) {
        int4 d = dst4[i];
        int base = i * 4;
        g_perm[atomicAdd(&g_cur[d.x], 1)] = base;
        g_perm[atomicAdd(&g_cur[d.y], 1)] = base + 1;
        g_perm[atomicAdd(&g_cur[d.z], 1)] = base + 2;
        g_perm[atomicAdd(&g_cur[d.w], 1)] = base + 3;
    }
    if (i < Nn) g_deg[i] = 0;          // deg no longer needed this call
    if (i == 0) g_ctr = 0;
}

// ---------------------------------------------------------------
// 9-shuffle reduction of 8 per-lane partials over the warp.
// Lane ends with full sum of value k(lane) = bitrev3(lane&7).
// Inverse map (source lane for k): SRC = {0,4,2,6,1,5,3,7}
// ---------------------------------------------------------------
__device__ __forceinline__ float reduce8_fast(float v[8], int lane) {
    bool b0 = lane & 1;
    float q0 = b0 ? v[4] : v[0], r0 = b0 ? v[0] : v[4];
    float q1 = b0 ? v[5] : v[1], r1 = b0 ? v[1] : v[5];
    float q2 = b0 ? v[6] : v[2], r2 = b0 ? v[2] : v[6];
    float q3 = b0 ? v[7] : v[3], r3 = b0 ? v[3] : v[7];
    q0 += __shfl_xor_sync(FULL, r0, 1);
    q1 += __shfl_xor_sync(FULL, r1, 1);
    q2 += __shfl_xor_sync(FULL, r2, 1);
    q3 += __shfl_xor_sync(FULL, r3, 1);
    bool b1 = lane & 2;
    float s0 = b1 ? q2 : q0, t0 = b1 ? q0 : q2;
    float s1 = b1 ? q3 : q1, t1 = b1 ? q1 : q3;
    s0 += __shfl_xor_sync(FULL, t0, 2);
    s1 += __shfl_xor_sync(FULL, t1, 2);
    bool b2 = lane & 4;
    float u0 = b2 ? s1 : s0, u1 = b2 ? s0 : s1;
    u0 += __shfl_xor_sync(FULL, u1, 4);
    u0 += __shfl_xor_sync(FULL, u0, 8);
    u0 += __shfl_xor_sync(FULL, u0, 16);
    return u0;
}

// ---------------------------------------------------------------
// K4: warp-per-node fused pass (proven R6 body).  Register-resident,
// no smem/blocksyncs.  Lane owns d = 4*lane..4*lane+3.  No max-
// subtraction softmax.  Depth-2 software pipeline on the edge gather.
// Edge range: [g_beg[n], g_cur[n])   (g_cur == end after scatter).
// ---------------------------------------------------------------
__global__ __launch_bounds__(128, 4) void k_agg(const float* __restrict__ ef,
                                                const float* __restrict__ nf,
                                                const float* __restrict__ Wr) {
    int t = threadIdx.x, lane = t & 31, w = t >> 5;
    int n = blockIdx.x * 4 + w;
    if (n >= Nn) return;

    float4 vv[Kk];
#pragma unroll
    for (int k = 0; k < Kk; ++k)
        vv[k] = ((const float4*)(g_v + k * Dd))[lane];

    float er_ln;
    {
        float4 x = ((const float4*)(nf + (size_t)n * Dd))[lane];
        float tk[Kk];
#pragma unroll
        for (int k = 0; k < Kk; ++k) {
            float4 wk = ((const float4*)(Wr + k * Dd))[lane];
            float s = x.x * wk.x;
            s = fmaf(x.y, wk.y, s);
            s = fmaf(x.z, wk.z, s);
            s = fmaf(x.w, wk.w, s);
            tk[k] = s;
        }
        er_ln = reduce8_fast(tk, lane);
    }

    float4 sl[Kk];
#pragma unroll
    for (int k = 0; k < Kk; ++k) sl[k] = make_float4(0.f, 0.f, 0.f, 0.f);
    float l_run = 0.f;

    int beg = g_beg[n];
    int end = g_cur[n];

#define LOADE(idx, A, B, C) do {                                             \
        int eid = g_perm[(idx)];                                             \
        const float4* src = (const float4*)(ef + (size_t)eid * (Ll * Dd));   \
        A = __ldcs(src + lane);                                              \
        B = __ldcs(src + lane + 32);                                         \
        C = __ldcs(src + lane + 64);                                         \
    } while (0)

#define STEP(EA, EB, EC) do {                                                \
        float4 s4;                                                           \
        s4.x = EA.x + EB.x + EC.x;                                           \
        s4.y = EA.y + EB.y + EC.y;                                           \
        s4.z = EA.z + EB.z + EC.z;                                           \
        s4.w = EA.w + EB.w + EC.w;                                           \
        float tk[Kk];                                                        \
        _Pragma("unroll")                                                    \
        for (int k = 0; k < Kk; ++k) {                                       \
            float s = s4.x * vv[k].x;                                        \
            s = fmaf(s4.y, vv[k].y, s);                                      \
            s = fmaf(s4.z, vv[k].z, s);                                      \
            s = fmaf(s4.w, vv[k].w, s);                                      \
            tk[k] = s;                                                       \
        }                                                                    \
        float e = reduce8_fast(tk, lane) + er_ln;                            \
        e = (e > 0.f) ? e : 0.01f * e;                                       \
        float p = __expf(e);                                                 \
        l_run += p;                                                          \
        _Pragma("unroll")                                                    \
        for (int k = 0; k < Kk; ++k) {                                       \
            float pk = __shfl_sync(FULL, p, SRC[k]);                         \
            sl[k].x = fmaf(pk, s4.x, sl[k].x);                               \
            sl[k].y = fmaf(pk, s4.y, sl[k].y);                               \
            sl[k].z = fmaf(pk, s4.z, sl[k].z);                               \
            sl[k].w = fmaf(pk, s4.w, sl[k].w);                               \
        }                                                                    \
    } while (0)

    constexpr int SRC[8] = {0, 4, 2, 6, 1, 5, 3, 7};

    float4 A0, B0, C0, A1, B1, C1;
    if (beg < end)     LOADE(beg, A0, B0, C0);
    if (beg + 1 < end) LOADE(beg + 1, A1, B1, C1);

    int i = beg;
    while (i < end) {
        {
            float4 ea = A0, eb = B0, ec = C0;
            if (i + 2 < end) LOADE(i + 2, A0, B0, C0);
            STEP(ea, eb, ec);
        }
        if (++i >= end) break;
        {
            float4 ea = A1, eb = B1, ec = C1;
            if (i + 2 < end) LOADE(i + 2, A1, B1, C1);
            STEP(ea, eb, ec);
        }
        ++i;
    }
#undef LOADE
#undef STEP

    float inv = (l_run > 0.f) ? (1.f / l_run) : 0.f;
#pragma unroll
    for (int k = 0; k < Kk; ++k) {
        float ik = __shfl_sync(FULL, inv, SRC[k]) * (1.f / 3.f);
        float4 o;
        o.x = sl[k].x * ik; o.y = sl[k].y * ik;
        o.z = sl[k].z * ik; o.w = sl[k].w * ik;
        ((float4*)(g_S + ((size_t)n * Kk + k) * Dd))[lane] = o;
    }
}

// ---------------------------------------------------------------
// K5: out[n,k,:] = S[n,k,:] @ W_enc[:, kH:kH+H]   (R12 body)
// Block: 128 nodes x 64 h for head kk.  128 threads, 8x8 microtiles.
// Inner product via fma.rn.f32x2 (packed dual-FP32).
// ---------------------------------------------------------------
__global__ __launch_bounds__(128) void k_gemm(const float* __restrict__ We,
                                              float* __restrict__ out) {
    __shared__ float Ssd[64][128];    // 32 KB, [d][node], d-major
    __shared__ float Wsh[64][64];     // 16 KB, [d][h]
    int t  = threadIdx.x;
    int kk = blockIdx.y;
    int n0 = blockIdx.x * 128;

    int tx = t & 7, ty = t >> 3;       // 8 x 16
    int i0 = ty * 8, h0 = tx * 8;

    unsigned long long acc2[8][4];
#pragma unroll
    for (int a = 0; a < 8; ++a)
#pragma unroll
        for (int b = 0; b < 4; ++b) acc2[a][b] = 0ull;

#pragma unroll
    for (int c = 0; c < 2; ++c) {
        __syncthreads();   // protect smem from previous chunk's compute

        // load W chunk: 1024 float4
#pragma unroll
        for (int j = 0; j < 8; ++j) {
            int wi = t + j * 128;
            int dd = wi >> 4;
            int hc = wi & 15;
            ((float4*)Wsh)[wi] =
                *((const float4*)(We + (size_t)(c * 64 + dd) * (Kk * Hh) + kk * Hh + hc * 4));
        }
        // load S chunk transposed: thread t owns node i = t
        {
            int n = n0 + t;
            if (n < Nn) {
                const float4* src =
                    (const float4*)(g_S + ((size_t)n * Kk + kk) * Dd + c * 64);
#pragma unroll
                for (int j = 0; j < 16; ++j) {
                    float4 v = src[j];
                    Ssd[j * 4 + 0][t] = v.x;
                    Ssd[j * 4 + 1][t] = v.y;
                    Ssd[j * 4 + 2][t] = v.z;
                    Ssd[j * 4 + 3][t] = v.w;
                }
            } else {
#pragma unroll
                for (int j = 0; j < 16; ++j) {
                    Ssd[j * 4 + 0][t] = 0.f;
                    Ssd[j * 4 + 1][t] = 0.f;
                    Ssd[j * 4 + 2][t] = 0.f;
                    Ssd[j * 4 + 3][t] = 0.f;
                }
            }
        }
        __syncthreads();

#pragma unroll 4
        for (int dd = 0; dd < 64; ++dd) {
            float4 a0 = *((const float4*)&Ssd[dd][i0]);
            float4 a1 = *((const float4*)&Ssd[dd][i0 + 4]);
            float4 b0 = *((const float4*)&Wsh[dd][h0]);
            float4 b1 = *((const float4*)&Wsh[dd][h0 + 4]);
            unsigned long long bp0, bp1, bp2, bp3;
            PK2(bp0, b0.x, b0.y);
            PK2(bp1, b0.z, b0.w);
            PK2(bp2, b1.x, b1.y);
            PK2(bp3, b1.z, b1.w);
            float av[8] = {a0.x, a0.y, a0.z, a0.w, a1.x, a1.y, a1.z, a1.w};
#pragma unroll
            for (int ii = 0; ii < 8; ++ii) {
                unsigned long long ap;
                PK2(ap, av[ii], av[ii]);
                FMA2(acc2[ii][0], ap, bp0);
                FMA2(acc2[ii][1], ap, bp1);
                FMA2(acc2[ii][2], ap, bp2);
                FMA2(acc2[ii][3], ap, bp3);
            }
        }
    }

#pragma unroll
    for (int ii = 0; ii < 8; ++ii) {
        int n = n0 + i0 + ii;
        if (n < Nn) {
            float o0, o1, o2, o3, o4, o5, o6, o7;
            UPK2(o0, o1, acc2[ii][0]);
            UPK2(o2, o3, acc2[ii][1]);
            UPK2(o4, o5, acc2[ii][2]);
            UPK2(o6, o7, acc2[ii][3]);
            float* dst = out + (size_t)n * (Kk * Hh) + kk * Hh + h0;
            *((float4*)dst)       = make_float4(o0, o1, o2, o3);
            *((float4*)(dst + 4)) = make_float4(o4, o5, o6, o7);
        }
    }
}

// ---------------------------------------------------------------
extern "C" void kernel_launch(void* const* d_in, const int* in_sizes, int n_in,
                              void* d_out, int out_size) {
    const float* node_feat = (const float*)d_in[0];   // (N,128)
    const float* edge_feat = (const float*)d_in[1];   // (E,3,128)
    const float* W_enc     = (const float*)d_in[2];   // (128,512)
    const float* attn_l    = (const float*)d_in[3];   // (1,8,64)
    const float* W_r       = (const float*)d_in[4];   // (8,128)
    const int*   dst       = (const int*)  d_in[5];   // (E,)
    float*       out       = (float*)d_out;           // (N,8,64)

    const int4* dst4 = (const int4*)dst;              // E % 4 == 0

    k_hist<<<(Ee / 4 + 255) / 256, 256>>>(dst4, W_enc, attn_l);
    k_off<<<(Nn + 255) / 256, 256>>>();
    k_scatter<<<(Ee / 4 + 255) / 256, 256>>>(dst4);
    k_agg<<<(Nn + 3) / 4, 128>>>(edge_feat, node_feat, W_r);
    k_gemm<<<dim3((Nn + 127) / 128, Kk), 128>>>(W_enc, out);
}